// round 2
// baseline (speedup 1.0000x reference)
#include <cuda_runtime.h>
#include <math.h>

// Problem shape (fixed by dataset): N=100000, H=32, K=15, C_in=C_out=64
#define MAXN 100000
#define NB_H 32
#define KPTS 15
#define CH   64

// Scratch (__device__ globals: allocation-free rule)
__device__ float4 g_pts4[MAXN];        // s_pts packed (w unused)
__device__ float4 g_q4[MAXN];          // q_pts packed, w = squared candidate threshold
__device__ float  g_val[MAXN * CH];    // raw kpconv rows for active points only
__device__ int    g_flag[MAXN];        // dedup flag
__device__ int    g_list[MAXN];        // active point list
__device__ int    g_cnt;
__device__ float  g_sum[CH], g_sumsq[CH];
__device__ float  g_mean[CH], g_inv[CH], g_z[CH];

static __host__ __device__ __forceinline__ float kp_extent() {
    return (float)(0.1 * 1.2 / 2.5);
}

// ---------------- init: pack points, zero state, bake threshold into q4.w ----------------
__global__ void __launch_bounds__(256) init_kernel(
    const float* __restrict__ q_pts, const float* __restrict__ s_pts,
    const float* __restrict__ kp, int N)
{
    __shared__ float s_n[16];
    const int tid = threadIdx.x;
    if (tid < KPTS) {
        float a = kp[3*tid], b = kp[3*tid+1], c = kp[3*tid+2];
        s_n[tid] = sqrtf(a*a + b*b + c*c);
    }
    if (tid == KPTS) s_n[KPTS] = 0.0f;
    __syncthreads();
    float mx = 0.0f;
#pragma unroll
    for (int k = 0; k < KPTS; k++) mx = fmaxf(mx, s_n[k]);
    const float t = (kp_extent() + mx) * 1.0002f + 1e-6f;  // false positives ok
    const float thr2 = t * t;

    const int i = blockIdx.x * 256 + tid;
    if (i == 0) g_cnt = 0;
    if (i < CH) { g_sum[i] = 0.0f; g_sumsq[i] = 0.0f; }
    if (i < N) {
        g_flag[i] = 0;
        g_pts4[i] = make_float4(s_pts[3*i], s_pts[3*i+1], s_pts[3*i+2], 0.0f);
        g_q4[i]   = make_float4(q_pts[3*i], q_pts[3*i+1], q_pts[3*i+2], thr2);
    }
}

// ---------------- pass 1: detect-only. 4 pairs/thread, float4 gathers ----------------
__global__ void __launch_bounds__(256) pass1_kernel(const int* __restrict__ inds, int N)
{
    const int t = blockIdx.x * 256 + threadIdx.x;   // thread handles pairs [4t, 4t+4)
    const int n = t >> 3;                           // 8 threads per point (H=32)
    if (n >= N) return;
    const int lane = threadIdx.x & 31;
    const unsigned FULL = 0xffffffffu;

    // q (+threshold in .w) loaded by one lane per point, shuffled to the other 7
    float4 q;
    if ((lane & 7) == 0) q = __ldg(&g_q4[n]);
    const int src = lane & ~7;
    q.x = __shfl_sync(FULL, q.x, src);
    q.y = __shfl_sync(FULL, q.y, src);
    q.z = __shfl_sync(FULL, q.z, src);
    q.w = __shfl_sync(FULL, q.w, src);

    const int4 iv = __ldg(reinterpret_cast<const int4*>(inds) + t);
    const int ids[4] = { iv.x, iv.y, iv.z, iv.w };

    bool any = false;
#pragma unroll
    for (int j = 0; j < 4; j++) {
        const int id = ids[j];
        if ((unsigned)id < (unsigned)N) {
            const float4 p = __ldg(&g_pts4[id]);
            const float dx = p.x - q.x, dy = p.y - q.y, dz = p.z - q.z;
            const float r2 = fmaf(dx, dx, fmaf(dy, dy, dz * dz));
            any |= (r2 < q.w);
        }
    }
    if (any) {
        if (atomicCAS(&g_flag[n], 0, 1) == 0) {
            const int p = atomicAdd(&g_cnt, 1);
            g_list[p] = n;
        }
    }
}

// ---------------- heavy: exact KPConv for the rare active points ----------------
__global__ void __launch_bounds__(256) heavy_kernel(
    const int*   __restrict__ inds,
    const float* __restrict__ x,
    const float* __restrict__ kp,
    const float* __restrict__ W,   // [K, C, C]
    int N)
{
    __shared__ float sw[8][KPTS][CH];   // 30 KB
    const int warp = threadIdx.x >> 5;
    const int lane = threadIdx.x & 31;
    const unsigned FULL = 0xffffffffu;

    const int cnt = __ldg(&g_cnt);
    const float EXT  = kp_extent();
    const float EXT2 = EXT * EXT;
    const float INVE = 1.0f / EXT;

    float kx[KPTS], ky[KPTS], kz[KPTS];
#pragma unroll
    for (int k = 0; k < KPTS; k++) {
        kx[k] = __ldg(kp + 3*k);
        ky[k] = __ldg(kp + 3*k + 1);
        kz[k] = __ldg(kp + 3*k + 2);
    }

    for (int e = blockIdx.x * 8 + warp; e < cnt; e += gridDim.x * 8) {
        const int n = g_list[e];
        const float4 q = __ldg(&g_q4[n]);

        const int idx = __ldg(inds + n * NB_H + lane);
        const bool valid = ((unsigned)idx < (unsigned)N);
        float nx = 1e9f, ny = 1e9f, nz = 1e9f;
        if (valid) {
            const float4 p = __ldg(&g_pts4[idx]);
            nx = p.x - q.x; ny = p.y - q.y; nz = p.z - q.z;
        }
        const float r2 = fmaf(nx, nx, fmaf(ny, ny, nz * nz));
        unsigned mask = __ballot_sync(FULL, valid && (r2 < q.w));

        float acc0[KPTS], acc1[KPTS];
#pragma unroll
        for (int k = 0; k < KPTS; k++) { acc0[k] = 0.0f; acc1[k] = 0.0f; }

        unsigned m = mask;
        while (m) {
            const int hs = __ffs(m) - 1;
            m &= (m - 1);
            const int   sidx = __shfl_sync(FULL, idx, hs);
            const float bx = __shfl_sync(FULL, nx, hs);
            const float by = __shfl_sync(FULL, ny, hs);
            const float bz = __shfl_sync(FULL, nz, hs);
            const float xv0 = __ldg(x + (long)sidx * CH + lane);
            const float xv1 = __ldg(x + (long)sidx * CH + lane + 32);
#pragma unroll
            for (int k = 0; k < KPTS; k++) {
                const float dx = bx - kx[k];
                const float dy = by - ky[k];
                const float dz = bz - kz[k];
                const float d2 = fmaf(dx, dx, fmaf(dy, dy, dz * dz));
                if (d2 < EXT2) {
                    const float w = fmaxf(1.0f - sqrtf(d2) * INVE, 0.0f);
                    acc0[k] = fmaf(w, xv0, acc0[k]);
                    acc1[k] = fmaf(w, xv1, acc1[k]);
                }
            }
        }

        unsigned kmask = 0;
#pragma unroll
        for (int k = 0; k < KPTS; k++) {
            sw[warp][k][lane]      = acc0[k];
            sw[warp][k][lane + 32] = acc1[k];
            if (__ballot_sync(FULL, (acc0[k] != 0.0f) || (acc1[k] != 0.0f)))
                kmask |= (1u << k);
        }
        __syncwarp();

        float o0 = 0.0f, o1 = 0.0f;
        for (int k = 0; k < KPTS; k++) {
            if (!(kmask & (1u << k))) continue;
            const float* Wk = W + (long)k * CH * CH;
#pragma unroll 8
            for (int c = 0; c < CH; c++) {
                const float wv = sw[warp][k][c];
                o0 = fmaf(wv, __ldg(Wk + c * CH + lane),      o0);
                o1 = fmaf(wv, __ldg(Wk + c * CH + lane + 32), o1);
            }
        }
        __syncwarp();

        g_val[(long)n * CH + lane]      = o0;
        g_val[(long)n * CH + lane + 32] = o1;
        atomicAdd(&g_sum[lane],        o0);
        atomicAdd(&g_sum[lane + 32],   o1);
        atomicAdd(&g_sumsq[lane],      o0 * o0);
        atomicAdd(&g_sumsq[lane + 32], o1 * o1);
    }
}

// ---------------- pass 2: finalize stats + normalized-zero constant ----------------
__global__ void pass2_kernel(int N) {
    const int t = threadIdx.x;  // 64 threads
    const float invN = 1.0f / (float)N;
    const float mean = g_sum[t] * invN;
    const float var  = fmaxf(g_sumsq[t] * invN - mean * mean, 0.0f);
    const float inv  = rsqrtf(var + 1e-5f);
    const float z    = (0.0f - mean) * inv;
    g_mean[t] = mean;
    g_inv[t]  = inv;
    g_z[t]    = (z >= 0.0f) ? z : 0.1f * z;
}

// ---------------- pass 3: pure constant stream-store (no per-row loads) ----------------
__global__ void __launch_bounds__(256) pass3_kernel(float4* __restrict__ out, int n4)
{
    __shared__ float4 cz[16];
    if (threadIdx.x < 16) {
        const int j = threadIdx.x * 4;
        cz[threadIdx.x] = make_float4(g_z[j], g_z[j+1], g_z[j+2], g_z[j+3]);
    }
    __syncthreads();
    const int base = blockIdx.x * (256 * 4) + threadIdx.x;
#pragma unroll
    for (int r = 0; r < 4; r++) {
        const int k = base + r * 256;
        if (k < n4) out[k] = cz[k & 15];
    }
}

// ---------------- fixup: overwrite active rows with normalized values ----------------
__global__ void __launch_bounds__(256) fixup_kernel(float* __restrict__ out)
{
    __shared__ float mm[CH], iv[CH];
    const int tid = threadIdx.x;
    if (tid < CH) { mm[tid] = g_mean[tid]; iv[tid] = g_inv[tid]; }
    __syncthreads();
    const int cnt = g_cnt;
    const int c = tid & 63;
    const int sub = tid >> 6;   // 4 rows in flight
    for (int e = sub; e < cnt; e += 4) {
        const int n = g_list[e];
        const float v = g_val[(long)n * CH + c];
        const float a = (v - mm[c]) * iv[c];
        out[(long)n * CH + c] = (a >= 0.0f) ? a : 0.1f * a;
    }
}

// ---------------- launch ----------------
extern "C" void kernel_launch(void* const* d_in, const int* in_sizes, int n_in,
                              void* d_out, int out_size) {
    const float* q_pts = (const float*)d_in[0];
    const float* s_pts = (const float*)d_in[1];
    const int*   inds  = (const int*)  d_in[2];
    const float* x     = (const float*)d_in[3];
    const float* kp    = (const float*)d_in[4];
    const float* W     = (const float*)d_in[5];
    float* out = (float*)d_out;

    const int N = in_sizes[0] / 3;

    init_kernel<<<(N + 255) / 256, 256>>>(q_pts, s_pts, kp, N);
    pass1_kernel<<<(N * 8 + 255) / 256, 256>>>(inds, N);
    heavy_kernel<<<32, 256>>>(inds, x, kp, W, N);
    pass2_kernel<<<1, CH>>>(N);
    const int n4 = N * (CH / 4);
    pass3_kernel<<<(n4 + 1023) / 1024, 256>>>((float4*)out, n4);
    fixup_kernel<<<1, 256>>>(out);
}